// round 12
// baseline (speedup 1.0000x reference)
#include <cuda_runtime.h>
#include <math.h>

#define LDIM 96           // L
#define FDIM 192          // 2L
#define TILE_R 96         // rows per tile (12 warps x TM=8)
#define NTHREADS 384      // 12 warps -> 3 warps/SMSP, reg ceiling 168
#define TM 8
#define KP1 48            // k-pairs GEMM1 (96/2)
#define KP2 96            // k-pairs GEMM2 (192/2)
#define PITCH 98          // float2 row pitch (even -> 16B-aligned LDS.128)

typedef unsigned long long ull;

// Folded DCT * W1 matrix (96 x 192), recomputed every launch (deterministic).
__device__ float g_M1[LDIM * FDIM];

__global__ void precompute_m1_kernel(const float* __restrict__ W1) {
    int n = blockIdx.x;    // 0..95
    int j = threadIdx.x;   // 0..191
    double base = 3.14159265358979323846 * (2.0 * (double)n + 1.0) / (2.0 * (double)LDIM);
    double acc = 0.0;
    for (int f = 0; f < LDIM; ++f)
        acc += 2.0 * cos(base * (double)f) * (double)W1[f * FDIM + j];
    g_M1[n * FDIM + j] = (float)acc;
}

// packed fp32x2 FMA: d = a*b + d (componentwise)
__device__ __forceinline__ void ffma2(ull& d, ull a, ull b) {
    asm volatile("fma.rn.f32x2 %0, %1, %2, %0;" : "+l"(d) : "l"(a), "l"(b));
}
__device__ __forceinline__ float f32x2_sum(ull v) {
    float lo, hi;
    asm("mov.b64 {%0, %1}, %2;" : "=f"(lo), "=f"(hi) : "l"(v));
    return lo + hi;
}

__global__ void __launch_bounds__(NTHREADS, 1)
fused_dct_mlp_ln_kernel(const float* __restrict__ x,
                        const float* __restrict__ W2,
                        const float* __restrict__ gamma,
                        const float* __restrict__ beta,
                        float* __restrict__ out,
                        int ntiles)
{
    extern __shared__ float2 smv2[];
    float2* M1p = smv2;                          // [48][192] f2   73,728 B
    float2* W2p = M1p + KP1 * FDIM;              // [96][96]  f2   73,728 B
    float2* HXs = W2p + KP2 * LDIM;              // union: Xs2 [48][98] / Hs2 [96][98]  75,264 B
    float2* Xs2 = HXs;
    float2* Hs2 = HXs;
    const ull* M1u = (const ull*)M1p;
    const ull* W2u = (const ull*)W2p;
    const ull* Xsu = (const ull*)Xs2;
    const ull* Hsu = (const ull*)Hs2;
    float* Hsf = (float*)Hs2;

    const int tid  = threadIdx.x;
    const int lane = tid & 31;
    const int wid  = tid >> 5;        // 0..11; each warp owns TM=8 rows
    const int r0   = wid * TM;

    // ---- One-time weight load, k-pair float2 repack ----
    {
        float* M1f = (float*)M1p;
        float* W2f = (float*)W2p;
        for (int i = tid; i < LDIM * FDIM; i += NTHREADS) {
            int k = i / FDIM, j = i - k * FDIM;
            M1f[(k >> 1) * (2 * FDIM) + 2 * j + (k & 1)] = g_M1[i];
        }
        for (int i = tid; i < FDIM * LDIM; i += NTHREADS) {
            int k = i / LDIM, n = i - k * LDIM;
            W2f[(k >> 1) * (2 * LDIM) + 2 * n + (k & 1)] = W2[i];
        }
    }
    float gm[3], bt[3];
    #pragma unroll
    for (int i = 0; i < 3; ++i) {
        gm[i] = gamma[lane + 32 * i];
        bt[i] = beta[lane + 32 * i];
    }
    __syncthreads();

    for (int tile = blockIdx.x; tile < ntiles; tile += gridDim.x) {
        // ---- 1) stage X tile (96 x 96), k-pair pack + transpose into Xs2[kp][row] ----
        {
            const float4* xg4 = (const float4*)(x + (size_t)tile * (TILE_R * LDIM));
            #pragma unroll
            for (int j = 0; j < (TILE_R * LDIM / 4) / NTHREADS; ++j) {  // 6 iters
                int i4 = tid + j * NTHREADS;
                float4 v = xg4[i4];
                int e = i4 * 4;
                int r = e / LDIM;
                int c = e - r * LDIM;       // multiple of 4, never crosses row
                int q = c >> 1;
                Xs2[(q + 0) * PITCH + r] = make_float2(v.x, v.y);
                Xs2[(q + 1) * PITCH + r] = make_float2(v.z, v.w);
            }
        }
        __syncthreads();

        // ---- 2) GEMM1 accumulate: H(96x192) = X @ M1, TM=8 x TN=6 ----
        ull acc1[TM][6];
        #pragma unroll
        for (int ii = 0; ii < TM; ++ii)
            #pragma unroll
            for (int i = 0; i < 6; ++i) acc1[ii][i] = 0ull;

        #pragma unroll 2
        for (int c = 0; c < KP1; ++c) {
            ulonglong2 A01 = *(const ulonglong2*)&Xsu[c * PITCH + r0];
            ulonglong2 A23 = *(const ulonglong2*)&Xsu[c * PITCH + r0 + 2];
            ulonglong2 A45 = *(const ulonglong2*)&Xsu[c * PITCH + r0 + 4];
            ulonglong2 A67 = *(const ulonglong2*)&Xsu[c * PITCH + r0 + 6];
            const ull* brow = &M1u[c * FDIM + lane];
            #pragma unroll
            for (int i = 0; i < 6; ++i) {
                ull b = brow[32 * i];          // LDS.64, lane-contiguous
                ffma2(acc1[0][i], A01.x, b);
                ffma2(acc1[1][i], A01.y, b);
                ffma2(acc1[2][i], A23.x, b);
                ffma2(acc1[3][i], A23.y, b);
                ffma2(acc1[4][i], A45.x, b);
                ffma2(acc1[5][i], A45.y, b);
                ffma2(acc1[6][i], A67.x, b);
                ffma2(acc1[7][i], A67.y, b);
            }
        }
        __syncthreads();   // all Xs reads complete -> safe to overwrite with Hs

        // ---- 3) relu + write H into k-pair-packed Hs2 (aliases Xs2) ----
        #pragma unroll
        for (int ii = 0; ii < TM; ++ii) {
            int rr = (r0 + ii) << 1;
            #pragma unroll
            for (int i = 0; i < 6; ++i) {
                float h = fmaxf(f32x2_sum(acc1[ii][i]), 0.f);
                int col = lane + 32 * i;
                Hsf[(col >> 1) * (2 * PITCH) + rr + (col & 1)] = h;
            }
        }
        __syncthreads();

        // ---- 4) GEMM2 accumulate: lr(96x96) = H @ W2, TM=8 x TN=3 ----
        {
            ull acc[TM][3];
            #pragma unroll
            for (int ii = 0; ii < TM; ++ii)
                #pragma unroll
                for (int i = 0; i < 3; ++i) acc[ii][i] = 0ull;

            #pragma unroll 2
            for (int c = 0; c < KP2; ++c) {
                ulonglong2 A01 = *(const ulonglong2*)&Hsu[c * PITCH + r0];
                ulonglong2 A23 = *(const ulonglong2*)&Hsu[c * PITCH + r0 + 2];
                ulonglong2 A45 = *(const ulonglong2*)&Hsu[c * PITCH + r0 + 4];
                ulonglong2 A67 = *(const ulonglong2*)&Hsu[c * PITCH + r0 + 6];
                const ull* wrow = &W2u[c * LDIM + lane];
                #pragma unroll
                for (int i = 0; i < 3; ++i) {
                    ull b = wrow[32 * i];
                    ffma2(acc[0][i], A01.x, b);
                    ffma2(acc[1][i], A01.y, b);
                    ffma2(acc[2][i], A23.x, b);
                    ffma2(acc[3][i], A23.y, b);
                    ffma2(acc[4][i], A45.x, b);
                    ffma2(acc[5][i], A45.y, b);
                    ffma2(acc[6][i], A67.x, b);
                    ffma2(acc[7][i], A67.y, b);
                }
            }

            // ---- 5) epilogue: prefetch x (L2 hit), sigmoid, LN, x*lr, store ----
            const size_t rowbase = (size_t)tile * TILE_R;
            float xr[TM][3];
            #pragma unroll
            for (int ii = 0; ii < TM; ++ii) {
                const float* xrow = x + (rowbase + (size_t)(r0 + ii)) * LDIM;
                xr[ii][0] = xrow[lane];
                xr[ii][1] = xrow[lane + 32];
                xr[ii][2] = xrow[lane + 64];
            }

            #pragma unroll
            for (int ii = 0; ii < TM; ++ii) {
                float v0 = __fdividef(1.f, 1.f + __expf(-f32x2_sum(acc[ii][0])));
                float v1 = __fdividef(1.f, 1.f + __expf(-f32x2_sum(acc[ii][1])));
                float v2 = __fdividef(1.f, 1.f + __expf(-f32x2_sum(acc[ii][2])));

                float s = v0 + v1 + v2;
                #pragma unroll
                for (int o = 16; o > 0; o >>= 1)
                    s += __shfl_xor_sync(0xffffffffu, s, o);
                float mu = s * (1.f / 96.f);

                float d0 = v0 - mu, d1 = v1 - mu, d2 = v2 - mu;
                float q = d0 * d0 + d1 * d1 + d2 * d2;
                #pragma unroll
                for (int o = 16; o > 0; o >>= 1)
                    q += __shfl_xor_sync(0xffffffffu, q, o);
                float inv = rsqrtf(q * (1.f / 96.f) + 1e-6f);

                size_t obase = (rowbase + (size_t)(r0 + ii)) * LDIM;
                out[obase + lane]      = xr[ii][0] * (d0 * inv * gm[0] + bt[0]);
                out[obase + lane + 32] = xr[ii][1] * (d1 * inv * gm[1] + bt[1]);
                out[obase + lane + 64] = xr[ii][2] * (d2 * inv * gm[2] + bt[2]);
            }
        }
        __syncthreads();   // all Hs reads complete before next tile's Xs staging
    }
}

extern "C" void kernel_launch(void* const* d_in, const int* in_sizes, int n_in,
                              void* d_out, int out_size) {
    const float* x     = (const float*)d_in[0];
    const float* W1    = (const float*)d_in[1];
    const float* W2    = (const float*)d_in[2];
    const float* gamma = (const float*)d_in[3];
    const float* beta  = (const float*)d_in[4];
    float* out = (float*)d_out;

    int rows   = in_sizes[0] / LDIM;     // 786432
    int ntiles = rows / TILE_R;          // 8192

    precompute_m1_kernel<<<LDIM, FDIM>>>(W1);

    const size_t smem_bytes =
        (size_t)(KP1 * FDIM + KP2 * LDIM + KP2 * PITCH) * sizeof(float2); // 222,720 B
    cudaFuncSetAttribute(fused_dct_mlp_ln_kernel,
                         cudaFuncAttributeMaxDynamicSharedMemorySize,
                         (int)smem_bytes);

    int nsm = 148;
    cudaDeviceGetAttribute(&nsm, cudaDevAttrMultiProcessorCount, 0);
    int grid = nsm < ntiles ? nsm : ntiles;

    fused_dct_mlp_ln_kernel<<<grid, NTHREADS, smem_bytes>>>(x, W2, gamma, beta, out, ntiles);
}

// round 13
// speedup vs baseline: 1.8608x; 1.8608x over previous
#include <cuda_runtime.h>
#include <cuda_bf16.h>
#include <math.h>
#include <stdint.h>

#define LDIM 96
#define FDIM 192
#define TILE_R 64
#define NTHREADS 256     // 8 warps = 4 m-blocks x 2 n-halves

// smem byte offsets (16B aligned); pitches chosen conflict-free:
//  P96 = 208 B  (k=96 arrays: row bases mod 128 = {0,80,32,112,64,16,96,48})
//  P192 = 400 B (k=192 arrays: row bases mod 128 = 16*g)
#define P96   208
#define P192  400
#define OFF_B1H 0                      // M1 hi: 192 n x 96 k bf16 (39,936)
#define OFF_B1L 39936
#define OFF_B2H 79872                  // W2^T hi: 96 n x 192 k bf16 (38,400)
#define OFF_B2L 118272
#define OFF_XH  156672                 // X hi: 64 x 96 bf16 (13,312)   [aliases H]
#define OFF_XL  169984
#define OFF_HH  156672                 // H hi: 64 x 192 bf16 (25,600)
#define OFF_HL  182272
#define OFF_S   207872                 // 2 x 64 f32
#define OFF_Q   208384                 // 2 x 64 f32
#define OFF_GAM 208896                 // 96 f32
#define OFF_BET 209280                 // 96 f32
#define SMEM_BYTES 209664

// Folded DCT * W1 (96 x 192), fp64 accumulation, recomputed every launch.
__device__ float g_M1[LDIM * FDIM];

__global__ void precompute_m1_kernel(const float* __restrict__ W1) {
    int n = blockIdx.x;
    int j = threadIdx.x;
    double base = 3.14159265358979323846 * (2.0 * (double)n + 1.0) / (2.0 * (double)LDIM);
    double acc = 0.0;
    for (int f = 0; f < LDIM; ++f)
        acc += 2.0 * cos(base * (double)f) * (double)W1[f * FDIM + j];
    g_M1[n * FDIM + j] = (float)acc;
}

__device__ __forceinline__ void mma_bf16(float* c, uint32_t a0, uint32_t a1,
                                         uint32_t a2, uint32_t a3,
                                         uint32_t b0, uint32_t b1) {
    asm volatile(
        "mma.sync.aligned.m16n8k16.row.col.f32.bf16.bf16.f32 "
        "{%0,%1,%2,%3}, {%4,%5,%6,%7}, {%8,%9}, {%0,%1,%2,%3};"
        : "+f"(c[0]), "+f"(c[1]), "+f"(c[2]), "+f"(c[3])
        : "r"(a0), "r"(a1), "r"(a2), "r"(a3), "r"(b0), "r"(b1));
}

// split v -> bf16 hi + bf16 lo (residual)
__device__ __forceinline__ void split1(float v, uint16_t& h, uint16_t& l) {
    __nv_bfloat16 hb = __float2bfloat16(v);
    __nv_bfloat16 lb = __float2bfloat16(v - __bfloat162float(hb));
    h = __bfloat16_as_ushort(hb);
    l = __bfloat16_as_ushort(lb);
}
__device__ __forceinline__ uint32_t pack2(uint16_t lo, uint16_t hi) {
    return (uint32_t)lo | ((uint32_t)hi << 16);
}

__global__ void __launch_bounds__(NTHREADS, 1)
fused_mma_kernel(const float* __restrict__ x,
                 const float* __restrict__ W2,
                 const float* __restrict__ gamma,
                 const float* __restrict__ beta,
                 float* __restrict__ out,
                 int ntiles)
{
    extern __shared__ char sm[];
    float* S   = (float*)(sm + OFF_S);
    float* Q   = (float*)(sm + OFF_Q);
    float* GAM = (float*)(sm + OFF_GAM);
    float* BET = (float*)(sm + OFF_BET);

    const int tid  = threadIdx.x;
    const int lane = tid & 31;
    const int wid  = tid >> 5;         // 0..7
    const int mi   = wid & 3;          // m16 block 0..3
    const int nh   = wid >> 2;         // n-half 0..1
    const int g    = lane >> 2;        // 0..7
    const int t    = lane & 3;         // 0..3
    const int M0   = mi * 16;

    // ---- one-time weight prep: bf16 hi/lo, conflict-free pitches ----
    for (int i = tid; i < LDIM * FDIM; i += NTHREADS) {      // B1[n][k] = M1[k][n]
        int k = i / FDIM, n = i - k * FDIM;
        uint16_t h, l; split1(g_M1[i], h, l);
        *(uint16_t*)(sm + OFF_B1H + n * P96 + k * 2) = h;
        *(uint16_t*)(sm + OFF_B1L + n * P96 + k * 2) = l;
    }
    for (int i = tid; i < FDIM * LDIM; i += NTHREADS) {      // B2[n][k] = W2[k][n]
        int k = i / LDIM, n = i - k * LDIM;
        uint16_t h, l; split1(W2[i], h, l);
        *(uint16_t*)(sm + OFF_B2H + n * P192 + k * 2) = h;
        *(uint16_t*)(sm + OFF_B2L + n * P192 + k * 2) = l;
    }
    if (tid < 96) { GAM[tid] = gamma[tid]; BET[tid] = beta[tid]; }
    __syncthreads();

    for (int tile = blockIdx.x; tile < ntiles; tile += gridDim.x) {
        const size_t rowbase = (size_t)tile * TILE_R;

        // ---- 1) stage X (64x96 fp32 -> bf16 hi/lo in smem) ----
        {
            const float4* xg = (const float4*)(x + rowbase * LDIM);
            #pragma unroll
            for (int it = 0; it < 6; ++it) {
                int i4 = tid + it * NTHREADS;
                float4 v = xg[i4];
                int e = i4 * 4, r = e / LDIM, c = e - LDIM * r;   // c % 4 == 0
                uint16_t hx, lx, hy, ly, hz, lz, hw, lw;
                split1(v.x, hx, lx); split1(v.y, hy, ly);
                split1(v.z, hz, lz); split1(v.w, hw, lw);
                *(uint32_t*)(sm + OFF_XH + r * P96 + c * 2)     = pack2(hx, hy);
                *(uint32_t*)(sm + OFF_XH + r * P96 + c * 2 + 4) = pack2(hz, hw);
                *(uint32_t*)(sm + OFF_XL + r * P96 + c * 2)     = pack2(lx, ly);
                *(uint32_t*)(sm + OFF_XL + r * P96 + c * 2 + 4) = pack2(lz, lw);
            }
        }
        __syncthreads();

        // ---- 2) GEMM1: D1(64x192) = X @ M1, split hh+hl+lh ----
        float acc1[12][4];
        #pragma unroll
        for (int j = 0; j < 12; ++j)
            #pragma unroll
            for (int p = 0; p < 4; ++p) acc1[j][p] = 0.f;

        #pragma unroll
        for (int ks = 0; ks < 6; ++ks) {
            int abyte = (M0 + g) * P96 + ks * 32 + 4 * t;
            uint32_t ah0 = *(const uint32_t*)(sm + OFF_XH + abyte);
            uint32_t ah1 = *(const uint32_t*)(sm + OFF_XH + abyte + 8 * P96);
            uint32_t ah2 = *(const uint32_t*)(sm + OFF_XH + abyte + 16);
            uint32_t ah3 = *(const uint32_t*)(sm + OFF_XH + abyte + 8 * P96 + 16);
            uint32_t al0 = *(const uint32_t*)(sm + OFF_XL + abyte);
            uint32_t al1 = *(const uint32_t*)(sm + OFF_XL + abyte + 8 * P96);
            uint32_t al2 = *(const uint32_t*)(sm + OFF_XL + abyte + 16);
            uint32_t al3 = *(const uint32_t*)(sm + OFF_XL + abyte + 8 * P96 + 16);
            #pragma unroll
            for (int j = 0; j < 12; ++j) {
                int bbyte = ((nh * 12 + j) * 8 + g) * P96 + ks * 32 + 4 * t;
                uint32_t bh0 = *(const uint32_t*)(sm + OFF_B1H + bbyte);
                uint32_t bh1 = *(const uint32_t*)(sm + OFF_B1H + bbyte + 16);
                uint32_t bl0 = *(const uint32_t*)(sm + OFF_B1L + bbyte);
                uint32_t bl1 = *(const uint32_t*)(sm + OFF_B1L + bbyte + 16);
                mma_bf16(acc1[j], ah0, ah1, ah2, ah3, bh0, bh1);
                mma_bf16(acc1[j], ah0, ah1, ah2, ah3, bl0, bl1);
                mma_bf16(acc1[j], al0, al1, al2, al3, bh0, bh1);
            }
        }
        __syncthreads();   // X reads done -> region becomes H

        // ---- 3) relu + split -> H hi/lo in smem ----
        #pragma unroll
        for (int j = 0; j < 12; ++j) {
            int N0 = (nh * 12 + j) * 8;
            float c0 = fmaxf(acc1[j][0], 0.f), c1 = fmaxf(acc1[j][1], 0.f);
            float c2 = fmaxf(acc1[j][2], 0.f), c3 = fmaxf(acc1[j][3], 0.f);
            uint16_t h0, l0, h1, l1; split1(c0, h0, l0); split1(c1, h1, l1);
            uint16_t h2, l2, h3, l3; split1(c2, h2, l2); split1(c3, h3, l3);
            int b0 = (M0 + g) * P192 + (N0 + 2 * t) * 2;
            int b1 = (M0 + g + 8) * P192 + (N0 + 2 * t) * 2;
            *(uint32_t*)(sm + OFF_HH + b0) = pack2(h0, h1);
            *(uint32_t*)(sm + OFF_HL + b0) = pack2(l0, l1);
            *(uint32_t*)(sm + OFF_HH + b1) = pack2(h2, h3);
            *(uint32_t*)(sm + OFF_HL + b1) = pack2(l2, l3);
        }
        __syncthreads();

        // ---- 4) GEMM2: D2(64x96) = H @ W2, split hh+hl+lh ----
        float acc2[6][4];
        #pragma unroll
        for (int j = 0; j < 6; ++j)
            #pragma unroll
            for (int p = 0; p < 4; ++p) acc2[j][p] = 0.f;

        #pragma unroll
        for (int ks = 0; ks < 12; ++ks) {
            int abyte = (M0 + g) * P192 + ks * 32 + 4 * t;
            uint32_t ah0 = *(const uint32_t*)(sm + OFF_HH + abyte);
            uint32_t ah1 = *(const uint32_t*)(sm + OFF_HH + abyte + 8 * P192);
            uint32_t ah2 = *(const uint32_t*)(sm + OFF_HH + abyte + 16);
            uint32_t ah3 = *(const uint32_t*)(sm + OFF_HH + abyte + 8 * P192 + 16);
            uint32_t al0 = *(const uint32_t*)(sm + OFF_HL + abyte);
            uint32_t al1 = *(const uint32_t*)(sm + OFF_HL + abyte + 8 * P192);
            uint32_t al2 = *(const uint32_t*)(sm + OFF_HL + abyte + 16);
            uint32_t al3 = *(const uint32_t*)(sm + OFF_HL + abyte + 8 * P192 + 16);
            #pragma unroll
            for (int j = 0; j < 6; ++j) {
                int bbyte = ((nh * 6 + j) * 8 + g) * P192 + ks * 32 + 4 * t;
                uint32_t bh0 = *(const uint32_t*)(sm + OFF_B2H + bbyte);
                uint32_t bh1 = *(const uint32_t*)(sm + OFF_B2H + bbyte + 16);
                uint32_t bl0 = *(const uint32_t*)(sm + OFF_B2L + bbyte);
                uint32_t bl1 = *(const uint32_t*)(sm + OFF_B2L + bbyte + 16);
                mma_bf16(acc2[j], ah0, ah1, ah2, ah3, bh0, bh1);
                mma_bf16(acc2[j], ah0, ah1, ah2, ah3, bl0, bl1);
                mma_bf16(acc2[j], al0, al1, al2, al3, bh0, bh1);
            }
        }

        // ---- 5) sigmoid + LayerNorm + x*lr ----
        {
            const int r0 = M0 + g, r1 = M0 + g + 8;
            float v[6][4];
            float p0 = 0.f, p1 = 0.f;
            #pragma unroll
            for (int j = 0; j < 6; ++j) {
                #pragma unroll
                for (int p = 0; p < 4; ++p)
                    v[j][p] = __fdividef(1.f, 1.f + __expf(-acc2[j][p]));
                p0 += v[j][0] + v[j][1];
                p1 += v[j][2] + v[j][3];
            }
            p0 += __shfl_xor_sync(0xffffffffu, p0, 1);
            p0 += __shfl_xor_sync(0xffffffffu, p0, 2);
            p1 += __shfl_xor_sync(0xffffffffu, p1, 1);
            p1 += __shfl_xor_sync(0xffffffffu, p1, 2);
            if (t == 0) { S[nh * 64 + r0] = p0; S[nh * 64 + r1] = p1; }
            __syncthreads();
            float mu0 = (S[r0] + S[64 + r0]) * (1.f / 96.f);
            float mu1 = (S[r1] + S[64 + r1]) * (1.f / 96.f);

            float q0 = 0.f, q1 = 0.f;
            #pragma unroll
            for (int j = 0; j < 6; ++j) {
                float d0 = v[j][0] - mu0, d1 = v[j][1] - mu0;
                float d2 = v[j][2] - mu1, d3 = v[j][3] - mu1;
                q0 += d0 * d0 + d1 * d1;
                q1 += d2 * d2 + d3 * d3;
            }
            q0 += __shfl_xor_sync(0xffffffffu, q0, 1);
            q0 += __shfl_xor_sync(0xffffffffu, q0, 2);
            q1 += __shfl_xor_sync(0xffffffffu, q1, 1);
            q1 += __shfl_xor_sync(0xffffffffu, q1, 2);
            if (t == 0) { Q[nh * 64 + r0] = q0; Q[nh * 64 + r1] = q1; }
            __syncthreads();
            float inv0 = rsqrtf((Q[r0] + Q[64 + r0]) * (1.f / 96.f) + 1e-6f);
            float inv1 = rsqrtf((Q[r1] + Q[64 + r1]) * (1.f / 96.f) + 1e-6f);

            #pragma unroll
            for (int j = 0; j < 6; ++j) {
                int col = (nh * 6 + j) * 8 + 2 * t;
                float2 gmv = *(const float2*)&GAM[col];
                float2 btv = *(const float2*)&BET[col];
                const float2* x0 = (const float2*)(x + (rowbase + r0) * LDIM + col);
                const float2* x1 = (const float2*)(x + (rowbase + r1) * LDIM + col);
                float2 xv0 = *x0, xv1 = *x1;
                float2 o0, o1;
                o0.x = xv0.x * ((v[j][0] - mu0) * inv0 * gmv.x + btv.x);
                o0.y = xv0.y * ((v[j][1] - mu0) * inv0 * gmv.y + btv.y);
                o1.x = xv1.x * ((v[j][2] - mu1) * inv1 * gmv.x + btv.x);
                o1.y = xv1.y * ((v[j][3] - mu1) * inv1 * gmv.y + btv.y);
                *(float2*)(out + (rowbase + r0) * LDIM + col) = o0;
                *(float2*)(out + (rowbase + r1) * LDIM + col) = o1;
            }
        }
        // no trailing sync needed: H reads finished before the S-barrier,
        // next tile's X staging is guarded by its own post-staging barrier
        // plus the Q-barrier above.
        __syncthreads();
    }
}

extern "C" void kernel_launch(void* const* d_in, const int* in_sizes, int n_in,
                              void* d_out, int out_size) {
    const float* x     = (const float*)d_in[0];
    const float* W1    = (const float*)d_in[1];
    const float* W2    = (const float*)d_in[2];
    const float* gamma = (const float*)d_in[3];
    const float* beta  = (const float*)d_in[4];
    float* out = (float*)d_out;

    int rows   = in_sizes[0] / LDIM;     // 786432
    int ntiles = rows / TILE_R;          // 12288

    precompute_m1_kernel<<<LDIM, FDIM>>>(W1);

    cudaFuncSetAttribute(fused_mma_kernel,
                         cudaFuncAttributeMaxDynamicSharedMemorySize, SMEM_BYTES);

    int nsm = 148;
    cudaDeviceGetAttribute(&nsm, cudaDevAttrMultiProcessorCount, 0);
    int grid = nsm < ntiles ? nsm : ntiles;

    fused_mma_kernel<<<grid, NTHREADS, SMEM_BYTES>>>(x, W2, gamma, beta, out, ntiles);
}